// round 13
// baseline (speedup 1.0000x reference)
#include <cuda_runtime.h>
#include <cuda_fp16.h>
#include <math.h>
#include <stdint.h>

#define B_   64
#define N_   196
#define C_   768
#define H_   12
#define HD_  64
#define TOPK_ 16
#define HID_ 3072
#define M_   (B_ * N_)          // 12544
#define SCALE_ 0.125f
#define EPS_ 1e-5f

// ---------------- scratch (device globals) ----------------
__device__ __half g_h_h  [(size_t)M_ * C_];
__device__ __half g_qk_h [(size_t)M_ * 2 * C_];
__device__ __half g_a_h  [(size_t)M_ * H_ * TOPK_];
__device__ float  g_x1   [(size_t)M_ * C_];
__device__ __half g_hid_h[(size_t)M_ * HID_];
// fp16 weights
__device__ __half g_qkw_h[(size_t)2 * C_ * C_];
__device__ __half g_pw_h [(size_t)C_ * H_ * TOPK_];
__device__ __half g_f1w_h[(size_t)HID_ * C_];
__device__ __half g_f2w_h[(size_t)C_ * HID_];

// ---------------- helpers ----------------
__device__ __forceinline__ void cp_async16(void* smem, const void* gmem) {
    uint32_t s = (uint32_t)__cvta_generic_to_shared(smem);
    asm volatile("cp.async.cg.shared.global [%0], [%1], 16;\n" :: "r"(s), "l"(gmem));
}
__device__ __forceinline__ void cp_commit() { asm volatile("cp.async.commit_group;\n"); }
template <int Np>
__device__ __forceinline__ void cp_wait() { asm volatile("cp.async.wait_group %0;\n" :: "n"(Np) : "memory"); }
__device__ __forceinline__ void ldsm4(uint32_t& r0, uint32_t& r1, uint32_t& r2, uint32_t& r3,
                                      uint32_t addr) {
    asm volatile("ldmatrix.sync.aligned.m8n8.x4.shared.b16 {%0,%1,%2,%3}, [%4];\n"
                 : "=r"(r0), "=r"(r1), "=r"(r2), "=r"(r3) : "r"(addr));
}
__device__ __forceinline__ uint32_t redux_max(uint32_t v) {
    uint32_t r;
    asm volatile("redux.sync.max.u32 %0, %1, 0xffffffff;\n" : "=r"(r) : "r"(v));
    return r;
}

// ---------------- merged weight fp32 -> fp16 (float4 vectorized) ----------------
__global__ void cvt4_kernel(const float* __restrict__ s0, __half* __restrict__ d0, int n0,
                            const float* __restrict__ s1, __half* __restrict__ d1, int n1,
                            const float* __restrict__ s2, __half* __restrict__ d2, int n2,
                            const float* __restrict__ s3, __half* __restrict__ d3, int n3) {
    int i = (blockIdx.x * 256 + threadIdx.x) * 4;
    const float* s; __half* d; int off;
    if (i < n0)                { s = s0; d = d0; off = 0; }
    else if (i < n0 + n1)      { s = s1; d = d1; off = n0; }
    else if (i < n0 + n1 + n2) { s = s2; d = d2; off = n0 + n1; }
    else if (i < n0 + n1 + n2 + n3) { s = s3; d = d3; off = n0 + n1 + n2; }
    else return;
    int j = i - off;
    float4 v = *(const float4*)&s[j];
    __half2 h0 = __floats2half2_rn(v.x, v.y);
    __half2 h1 = __floats2half2_rn(v.z, v.w);
    *(uint2*)&d[j] = make_uint2(*(uint32_t*)&h0, *(uint32_t*)&h1);
}

// ---------------- LayerNorm -> fp16 (float4 vectorized, 192 threads) ----------------
__global__ void ln_kernel(const float* __restrict__ x, const float* __restrict__ g,
                          const float* __restrict__ b, __half* __restrict__ out) {
    int row = blockIdx.x;
    const float4* xr = (const float4*)(x + (size_t)row * C_);
    int tid = threadIdx.x, lane = tid & 31, warp = tid >> 5;   // 192 threads, 6 warps

    float4 v = xr[tid];
    float s  = v.x + v.y + v.z + v.w;
    float s2 = v.x * v.x + v.y * v.y + v.z * v.z + v.w * v.w;
    #pragma unroll
    for (int o = 16; o > 0; o >>= 1) {
        s  += __shfl_xor_sync(0xffffffffu, s,  o);
        s2 += __shfl_xor_sync(0xffffffffu, s2, o);
    }
    __shared__ float shs[6], shs2[6], sh_mu, sh_inv;
    if (lane == 0) { shs[warp] = s; shs2[warp] = s2; }
    __syncthreads();
    if (tid == 0) {
        float ts = 0.f, ts2 = 0.f;
        #pragma unroll
        for (int w = 0; w < 6; w++) { ts += shs[w]; ts2 += shs2[w]; }
        float mu = ts / C_;
        sh_mu = mu; sh_inv = rsqrtf(ts2 / C_ - mu * mu + EPS_);
    }
    __syncthreads();
    float mu = sh_mu, inv = sh_inv;
    float4 gv = ((const float4*)g)[tid];
    float4 bv = ((const float4*)b)[tid];
    float o0 = (v.x - mu) * inv * gv.x + bv.x;
    float o1 = (v.y - mu) * inv * gv.y + bv.y;
    float o2 = (v.z - mu) * inv * gv.z + bv.z;
    float o3 = (v.w - mu) * inv * gv.w + bv.w;
    __half2 h0 = __floats2half2_rn(o0, o1);
    __half2 h1 = __floats2half2_rn(o2, o3);
    *(uint2*)&out[(size_t)row * C_ + tid * 4] = make_uint2(*(uint32_t*)&h0, *(uint32_t*)&h1);
}

// ---------------- FP16 mma.sync GEMM (frag double-buffered) ----------------
#define STG_B 32768               // (128+128) rows * 128 B
#define NSTG  3
#define SMEM_SZ (NSTG * STG_B)

template <bool BIAS, bool GELU, bool RES, bool OUTH>
__global__ __launch_bounds__(128, 2) void gemm_h(
        const __half* __restrict__ A, const __half* __restrict__ W,
        const float* __restrict__ bias, const float* __restrict__ res,
        float* __restrict__ outf, __half* __restrict__ outh, int Nout, int K) {
    extern __shared__ char smem[];
    uint32_t sb = (uint32_t)__cvta_generic_to_shared(smem);

    int tid = threadIdx.x;
    int lane = tid & 31, wid = tid >> 5;
    int wr = wid >> 1, wc = wid & 1;
    int g = lane >> 2, t = lane & 3;
    int grp = lane >> 3, l7 = lane & 7;
    int bm = blockIdx.y * 128, bn = blockIdx.x * 128;

    const __half* Ablk = A + (size_t)bm * K;
    const __half* Wblk = W + (size_t)bn * K;

    float c[4][8][4];
    #pragma unroll
    for (int i = 0; i < 4; i++)
        #pragma unroll
        for (int j = 0; j < 8; j++)
            #pragma unroll
            for (int r = 0; r < 4; r++) c[i][j][r] = 0.f;

    int lrow0 = tid >> 3;
    int lseg  = tid & 7;
    uint32_t lcol = (uint32_t)((lseg ^ (lrow0 & 7)) << 4);
    auto load_stage = [&](int slot, int k0) {
        char* sbase = smem + slot * STG_B;
        #pragma unroll
        for (int i = 0; i < 16; i++) {
            int row = lrow0 + (i & 7) * 16;
            int isB = i >> 3;
            const __half* src = (isB ? Wblk : Ablk) + (size_t)row * K + k0 + lseg * 8;
            char* dst = sbase + isB * 16384 + row * 128 + lcol;
            cp_async16(dst, src);
        }
        cp_commit();
    };

    int NK = K / 64;
    load_stage(0, 0);
    load_stage(1, 64);

    int rowoffA = (grp & 1) * 8, segoffA = grp >> 1;
    int rowoffB = (grp >> 1) * 8, segoffB = grp & 1;

    uint32_t afr[2][4][4], bfr[2][8][2];

    auto load_frags = [&](int j, int buf, uint32_t sA, uint32_t sB) {
        #pragma unroll
        for (int ti = 0; ti < 4; ti++) {
            int row = wr * 64 + ti * 16 + rowoffA + l7;
            uint32_t addr = sA + (row << 7) + (((2 * j + segoffA) ^ (row & 7)) << 4);
            ldsm4(afr[buf][ti][0], afr[buf][ti][1], afr[buf][ti][2], afr[buf][ti][3], addr);
        }
        #pragma unroll
        for (int tp = 0; tp < 4; tp++) {
            int row = wc * 64 + tp * 16 + rowoffB + l7;
            uint32_t addr = sB + (row << 7) + (((2 * j + segoffB) ^ (row & 7)) << 4);
            uint32_t r0, r1, r2, r3;
            ldsm4(r0, r1, r2, r3, addr);
            bfr[buf][2 * tp][0] = r0;     bfr[buf][2 * tp][1] = r1;
            bfr[buf][2 * tp + 1][0] = r2; bfr[buf][2 * tp + 1][1] = r3;
        }
    };

    for (int kc = 0; kc < NK; kc++) {
        int slot = kc % NSTG;
        cp_wait<1>();
        __syncthreads();

        if (kc + 2 < NK) load_stage((kc + 2) % NSTG, (kc + 2) * 64);
        else cp_commit();

        uint32_t sA = sb + slot * STG_B;
        uint32_t sB = sA + 16384;

        load_frags(0, 0, sA, sB);
        #pragma unroll
        for (int j = 0; j < 4; j++) {
            int cur = j & 1;
            if (j < 3) load_frags(j + 1, cur ^ 1, sA, sB);
            #pragma unroll
            for (int ti = 0; ti < 4; ti++)
                #pragma unroll
                for (int tj = 0; tj < 8; tj++) {
                    asm volatile(
                        "mma.sync.aligned.m16n8k16.row.col.f32.f16.f16.f32 "
                        "{%0,%1,%2,%3}, {%4,%5,%6,%7}, {%8,%9}, {%0,%1,%2,%3};\n"
                        : "+f"(c[ti][tj][0]), "+f"(c[ti][tj][1]),
                          "+f"(c[ti][tj][2]), "+f"(c[ti][tj][3])
                        : "r"(afr[cur][ti][0]), "r"(afr[cur][ti][1]),
                          "r"(afr[cur][ti][2]), "r"(afr[cur][ti][3]),
                          "r"(bfr[cur][tj][0]), "r"(bfr[cur][tj][1]));
                }
        }
    }

    // epilogue
    #pragma unroll
    for (int ti = 0; ti < 4; ti++) {
        int r0 = bm + wr * 64 + ti * 16 + g;
        #pragma unroll
        for (int tj = 0; tj < 8; tj++) {
            int cn = bn + wc * 64 + tj * 8 + t * 2;
            float v[4] = {c[ti][tj][0], c[ti][tj][1], c[ti][tj][2], c[ti][tj][3]};
            if (BIAS) {
                float b0 = bias[cn], b1 = bias[cn + 1];
                v[0] += b0; v[1] += b1; v[2] += b0; v[3] += b1;
            }
            if (GELU) {
                #pragma unroll
                for (int q = 0; q < 4; q++)
                    v[q] = 0.5f * v[q] * (1.0f + erff(v[q] * 0.70710678118654752f));
            }
            if (RES) {
                float2 r0v = *(const float2*)&res[(size_t)r0 * Nout + cn];
                float2 r1v = *(const float2*)&res[(size_t)(r0 + 8) * Nout + cn];
                v[0] += r0v.x; v[1] += r0v.y; v[2] += r1v.x; v[3] += r1v.y;
            }
            if (OUTH) {
                *(__half2*)&outh[(size_t)r0 * Nout + cn]       = __floats2half2_rn(v[0], v[1]);
                *(__half2*)&outh[(size_t)(r0 + 8) * Nout + cn] = __floats2half2_rn(v[2], v[3]);
            } else {
                *(float2*)&outf[(size_t)r0 * Nout + cn]       = make_float2(v[0], v[1]);
                *(float2*)&outf[(size_t)(r0 + 8) * Nout + cn] = make_float2(v[2], v[3]);
            }
        }
    }
}

// ---------------- fused attention v3: 2 rows/warp K-reuse + redux.sync top-16 ----------------
#define KS_STRIDE 33
__global__ __launch_bounds__(256) void attn_topk_kernel(const __half* __restrict__ qk,
                                                        __half* __restrict__ a) {
    int bh = blockIdx.x;
    int b = bh / H_, h = bh % H_;
    extern __shared__ uint32_t sm2[];
    uint32_t* Qs2 = sm2;              // [196][32] half2, pre-scaled
    uint32_t* Ks2 = sm2 + N_ * 32;    // [196][33] half2 (padded)

    int tid = threadIdx.x, lane = tid & 31, warp = tid >> 5;

    const __half* base = qk + (size_t)b * N_ * (2 * C_);
    const __half2 sc = __float2half2_rn(SCALE_);
    for (int e = tid; e < N_ * 32; e += 256) {
        int n = e >> 5, dp = e & 31;
        __half2 qh = *(const __half2*)&base[(size_t)n * (2 * C_) + h * HD_ + dp * 2];
        qh = __hmul2(qh, sc);
        Qs2[n * 32 + dp] = *(uint32_t*)&qh;
        Ks2[n * KS_STRIDE + dp] = *(const uint32_t*)&base[(size_t)n * (2 * C_) + C_ + h * HD_ + dp * 2];
    }
    __syncthreads();

    // each warp handles row pair (i0, i0+98); K loads shared between the pair
    for (int i0 = warp; i0 < 98; i0 += 8) {
        int iB = i0 + 98;
        int jj[7];
        #pragma unroll
        for (int t = 0; t < 7; t++) {
            int j = lane + 32 * t;
            jj[t] = (j < N_) ? j * KS_STRIDE : 0;
        }
        __half2 aA0[7], aA1[7], aB0[7], aB1[7];
        #pragma unroll
        for (int t = 0; t < 7; t++) {
            aA0[t] = __float2half2_rn(0.f); aA1[t] = __float2half2_rn(0.f);
            aB0[t] = __float2half2_rn(0.f); aB1[t] = __float2half2_rn(0.f);
        }
        const uint32_t* qrA = Qs2 + i0 * 32;
        const uint32_t* qrB = Qs2 + iB * 32;
        #pragma unroll 4
        for (int dp = 0; dp < 32; dp += 2) {
            uint32_t qa0u = qrA[dp], qa1u = qrA[dp + 1];
            uint32_t qb0u = qrB[dp], qb1u = qrB[dp + 1];
            __half2 qa0 = *(__half2*)&qa0u, qa1 = *(__half2*)&qa1u;
            __half2 qb0 = *(__half2*)&qb0u, qb1 = *(__half2*)&qb1u;
            #pragma unroll
            for (int t = 0; t < 7; t++) {
                uint32_t k0 = Ks2[jj[t] + dp];
                uint32_t k1 = Ks2[jj[t] + dp + 1];
                __half2 k0h = *(__half2*)&k0, k1h = *(__half2*)&k1;
                aA0[t] = __hfma2(qa0, k0h, aA0[t]);
                aA1[t] = __hfma2(qa1, k1h, aA1[t]);
                aB0[t] = __hfma2(qb0, k0h, aB0[t]);
                aB1[t] = __hfma2(qb1, k1h, aB1[t]);
            }
        }
        // pack to ordered uints with id in low 8 bits
        uint32_t pA[7], pB[7];
        #pragma unroll
        for (int t = 0; t < 7; t++) {
            uint32_t id = (uint32_t)(lane << 3) | (uint32_t)t;
            bool ok = (lane + 32 * t < N_);
            float2 f0 = __half22float2(aA0[t]);
            float2 f1 = __half22float2(aA1[t]);
            float s = (f0.x + f0.y) + (f1.x + f1.y);
            uint32_t ub = __float_as_uint(s);
            ub = (s >= 0.f) ? (ub | 0x80000000u) : ~ub;
            pA[t] = ok ? ((ub & 0xFFFFFF00u) | id) : 0u;
            f0 = __half22float2(aB0[t]);
            f1 = __half22float2(aB1[t]);
            s = (f0.x + f0.y) + (f1.x + f1.y);
            ub = __float_as_uint(s);
            ub = (s >= 0.f) ? (ub | 0x80000000u) : ~ub;
            pB[t] = ok ? ((ub & 0xFFFFFF00u) | id) : 0u;
        }
        float topA[16], topB[16];
        #pragma unroll
        for (int sel = 0; sel < TOPK_; sel++) {
            uint32_t mA = pA[0], mB = pB[0];
            #pragma unroll
            for (int t = 1; t < 7; t++) {
                mA = (pA[t] > mA) ? pA[t] : mA;
                mB = (pB[t] > mB) ? pB[t] : mB;
            }
            mA = redux_max(mA);
            mB = redux_max(mB);
            uint32_t ubA = mA & 0xFFFFFF00u, ubB = mB & 0xFFFFFF00u;
            topA[sel] = (ubA & 0x80000000u) ? __uint_as_float(ubA & 0x7FFFFFFFu) : __uint_as_float(~ubA);
            topB[sel] = (ubB & 0x80000000u) ? __uint_as_float(ubB & 0x7FFFFFFFu) : __uint_as_float(~ubB);
            if (lane == (int)((mA >> 3) & 31u)) {
                int sl = (int)(mA & 7u);
                #pragma unroll
                for (int t = 0; t < 7; t++) if (t == sl) pA[t] = 0u;
            }
            if (lane == (int)((mB >> 3) & 31u)) {
                int sl = (int)(mB & 7u);
                #pragma unroll
                for (int t = 0; t < 7; t++) if (t == sl) pB[t] = 0u;
            }
        }
        float sA = 0.f, sB = 0.f;
        #pragma unroll
        for (int t = 0; t < TOPK_; t++) {
            sA += expf(topA[t] - topA[0]);
            sB += expf(topB[t] - topB[0]);
        }
        if (lane < TOPK_) {
            float vA = expf(topA[lane] - topA[0]) / sA;
            float vB = expf(topB[lane] - topB[0]) / sB;
            a[((size_t)(b * N_ + i0)) * (H_ * TOPK_) + h * TOPK_ + lane] = __float2half(vA);
            a[((size_t)(b * N_ + iB)) * (H_ * TOPK_) + h * TOPK_ + lane] = __float2half(vB);
        }
    }
}

// ---------------- launch ----------------
extern "C" void kernel_launch(void* const* d_in, const int* in_sizes, int n_in,
                              void* d_out, int out_size) {
    const float* x      = (const float*)d_in[0];
    const float* n1g    = (const float*)d_in[1];
    const float* n1b    = (const float*)d_in[2];
    const float* qk_w   = (const float*)d_in[3];
    const float* proj_w = (const float*)d_in[4];
    const float* proj_b = (const float*)d_in[5];
    const float* n2g    = (const float*)d_in[6];
    const float* n2b    = (const float*)d_in[7];
    const float* fc1_w  = (const float*)d_in[8];
    const float* fc1_b  = (const float*)d_in[9];
    const float* fc2_w  = (const float*)d_in[10];
    const float* fc2_b  = (const float*)d_in[11];
    float* out = (float*)d_out;

    __half *h_h, *qk_h, *a_h, *hid_h, *qkw_h, *pw_h, *f1w_h, *f2w_h;
    float *x1;
    cudaGetSymbolAddress((void**)&h_h,   g_h_h);
    cudaGetSymbolAddress((void**)&qk_h,  g_qk_h);
    cudaGetSymbolAddress((void**)&a_h,   g_a_h);
    cudaGetSymbolAddress((void**)&x1,    g_x1);
    cudaGetSymbolAddress((void**)&hid_h, g_hid_h);
    cudaGetSymbolAddress((void**)&qkw_h, g_qkw_h);
    cudaGetSymbolAddress((void**)&pw_h,  g_pw_h);
    cudaGetSymbolAddress((void**)&f1w_h, g_f1w_h);
    cudaGetSymbolAddress((void**)&f2w_h, g_f2w_h);

    cudaFuncSetAttribute((const void*)gemm_h<false,false,false,true>, cudaFuncAttributeMaxDynamicSharedMemorySize, SMEM_SZ);
    cudaFuncSetAttribute((const void*)gemm_h<true,false,true,false>,  cudaFuncAttributeMaxDynamicSharedMemorySize, SMEM_SZ);
    cudaFuncSetAttribute((const void*)gemm_h<true,true,false,true>,   cudaFuncAttributeMaxDynamicSharedMemorySize, SMEM_SZ);

    // merged weight conversions (fp32 -> fp16)
    {
        int n0 = 2 * C_ * C_;
        int n1 = C_ * H_ * TOPK_;
        int n2 = HID_ * C_;
        int n3 = C_ * HID_;
        int total = n0 + n1 + n2 + n3;
        cvt4_kernel<<<(total / 4 + 255) / 256, 256>>>(qk_w, qkw_h, n0,
                                                      proj_w, pw_h, n1,
                                                      fc1_w, f1w_h, n2,
                                                      fc2_w, f2w_h, n3);
    }

    // 1. LN1 -> fp16
    ln_kernel<<<M_, 192>>>(x, n1g, n1b, h_h);

    // 2. qk = h @ qk_w^T   [M, 1536], K=768 (fp16 out)
    gemm_h<false, false, false, true><<<dim3((2 * C_) / 128, M_ / 128), 128, SMEM_SZ>>>(
        h_h, qkw_h, nullptr, nullptr, nullptr, qk_h, 2 * C_, C_);

    // 3. attention -> a fp16 [M, 192]
    int smem = N_ * 32 * 4 + N_ * KS_STRIDE * 4;  // 50960 B
    cudaFuncSetAttribute(attn_topk_kernel, cudaFuncAttributeMaxDynamicSharedMemorySize, smem);
    attn_topk_kernel<<<B_ * H_, 256, smem>>>(qk_h, a_h);

    // 4. x1 = x + a @ proj_w^T + proj_b   [M, 768], K=192
    gemm_h<true, false, true, false><<<dim3(C_ / 128, M_ / 128), 128, SMEM_SZ>>>(
        a_h, pw_h, proj_b, x, x1, nullptr, C_, H_ * TOPK_);

    // 5. LN2 -> fp16
    ln_kernel<<<M_, 192>>>(x1, n2g, n2b, h_h);

    // 6. hid = gelu(h @ fc1_w^T + fc1_b) -> fp16 [M, 3072], K=768
    gemm_h<true, true, false, true><<<dim3(HID_ / 128, M_ / 128), 128, SMEM_SZ>>>(
        h_h, f1w_h, fc1_b, nullptr, nullptr, hid_h, HID_, C_);

    // 7. out = x1 + hid @ fc2_w^T + fc2_b  [M, 768], K=3072
    gemm_h<true, false, true, false><<<dim3(C_ / 128, M_ / 128), 128, SMEM_SZ>>>(
        hid_h, f2w_h, fc2_b, x1, out, nullptr, C_, HID_);
}

// round 15
// speedup vs baseline: 1.3463x; 1.3463x over previous
#include <cuda_runtime.h>
#include <cuda_fp16.h>
#include <math.h>
#include <stdint.h>

#define B_   64
#define N_   196
#define C_   768
#define H_   12
#define HD_  64
#define TOPK_ 16
#define HID_ 3072
#define M_   (B_ * N_)          // 12544
#define SCALE_ 0.125f
#define EPS_ 1e-5f

// ---------------- scratch (device globals) ----------------
__device__ __half g_h_h  [(size_t)M_ * C_];
__device__ __half g_qk_h [(size_t)M_ * 2 * C_];
__device__ __half g_a_h  [(size_t)M_ * H_ * TOPK_];
__device__ float  g_x1   [(size_t)M_ * C_];
__device__ __half g_hid_h[(size_t)M_ * HID_];
// fp16 weights
__device__ __half g_qkw_h[(size_t)2 * C_ * C_];
__device__ __half g_pw_h [(size_t)C_ * H_ * TOPK_];
__device__ __half g_f1w_h[(size_t)HID_ * C_];
__device__ __half g_f2w_h[(size_t)C_ * HID_];

// ---------------- helpers ----------------
__device__ __forceinline__ void cp_async16(void* smem, const void* gmem) {
    uint32_t s = (uint32_t)__cvta_generic_to_shared(smem);
    asm volatile("cp.async.cg.shared.global [%0], [%1], 16;\n" :: "r"(s), "l"(gmem));
}
__device__ __forceinline__ void cp_async16a(uint32_t s, const void* gmem) {
    asm volatile("cp.async.cg.shared.global [%0], [%1], 16;\n" :: "r"(s), "l"(gmem));
}
__device__ __forceinline__ void cp_commit() { asm volatile("cp.async.commit_group;\n"); }
template <int Np>
__device__ __forceinline__ void cp_wait() { asm volatile("cp.async.wait_group %0;\n" :: "n"(Np) : "memory"); }
__device__ __forceinline__ void ldsm4(uint32_t& r0, uint32_t& r1, uint32_t& r2, uint32_t& r3,
                                      uint32_t addr) {
    asm volatile("ldmatrix.sync.aligned.m8n8.x4.shared.b16 {%0,%1,%2,%3}, [%4];\n"
                 : "=r"(r0), "=r"(r1), "=r"(r2), "=r"(r3) : "r"(addr));
}
__device__ __forceinline__ void sts32(uint32_t addr, uint32_t val) {
    asm volatile("st.shared.b32 [%0], %1;\n" :: "r"(addr), "r"(val) : "memory");
}

// ---------------- merged weight fp32 -> fp16 (float4 vectorized) ----------------
__global__ void cvt4_kernel(const float* __restrict__ s0, __half* __restrict__ d0, int n0,
                            const float* __restrict__ s1, __half* __restrict__ d1, int n1,
                            const float* __restrict__ s2, __half* __restrict__ d2, int n2,
                            const float* __restrict__ s3, __half* __restrict__ d3, int n3) {
    int i = (blockIdx.x * 256 + threadIdx.x) * 4;
    const float* s; __half* d; int off;
    if (i < n0)                { s = s0; d = d0; off = 0; }
    else if (i < n0 + n1)      { s = s1; d = d1; off = n0; }
    else if (i < n0 + n1 + n2) { s = s2; d = d2; off = n0 + n1; }
    else if (i < n0 + n1 + n2 + n3) { s = s3; d = d3; off = n0 + n1 + n2; }
    else return;
    int j = i - off;
    float4 v = *(const float4*)&s[j];
    __half2 h0 = __floats2half2_rn(v.x, v.y);
    __half2 h1 = __floats2half2_rn(v.z, v.w);
    *(uint2*)&d[j] = make_uint2(*(uint32_t*)&h0, *(uint32_t*)&h1);
}

// ---------------- LayerNorm -> fp16 (float4 vectorized, 192 threads) ----------------
__global__ void ln_kernel(const float* __restrict__ x, const float* __restrict__ g,
                          const float* __restrict__ b, __half* __restrict__ out) {
    int row = blockIdx.x;
    const float4* xr = (const float4*)(x + (size_t)row * C_);
    int tid = threadIdx.x, lane = tid & 31, warp = tid >> 5;   // 192 threads, 6 warps

    float4 v = xr[tid];
    float s  = v.x + v.y + v.z + v.w;
    float s2 = v.x * v.x + v.y * v.y + v.z * v.z + v.w * v.w;
    #pragma unroll
    for (int o = 16; o > 0; o >>= 1) {
        s  += __shfl_xor_sync(0xffffffffu, s,  o);
        s2 += __shfl_xor_sync(0xffffffffu, s2, o);
    }
    __shared__ float shs[6], shs2[6], sh_mu, sh_inv;
    if (lane == 0) { shs[warp] = s; shs2[warp] = s2; }
    __syncthreads();
    if (tid == 0) {
        float ts = 0.f, ts2 = 0.f;
        #pragma unroll
        for (int w = 0; w < 6; w++) { ts += shs[w]; ts2 += shs2[w]; }
        float mu = ts / C_;
        sh_mu = mu; sh_inv = rsqrtf(ts2 / C_ - mu * mu + EPS_);
    }
    __syncthreads();
    float mu = sh_mu, inv = sh_inv;
    float4 gv = ((const float4*)g)[tid];
    float4 bv = ((const float4*)b)[tid];
    float o0 = (v.x - mu) * inv * gv.x + bv.x;
    float o1 = (v.y - mu) * inv * gv.y + bv.y;
    float o2 = (v.z - mu) * inv * gv.z + bv.z;
    float o3 = (v.w - mu) * inv * gv.w + bv.w;
    __half2 h0 = __floats2half2_rn(o0, o1);
    __half2 h1 = __floats2half2_rn(o2, o3);
    *(uint2*)&out[(size_t)row * C_ + tid * 4] = make_uint2(*(uint32_t*)&h0, *(uint32_t*)&h1);
}

// ---------------- FP16 mma.sync GEMM (frag double-buffered) ----------------
#define STG_B 32768               // (128+128) rows * 128 B
#define NSTG  3
#define SMEM_SZ (NSTG * STG_B)

template <bool BIAS, bool GELU, bool RES, bool OUTH>
__global__ __launch_bounds__(128, 2) void gemm_h(
        const __half* __restrict__ A, const __half* __restrict__ W,
        const float* __restrict__ bias, const float* __restrict__ res,
        float* __restrict__ outf, __half* __restrict__ outh, int Nout, int K) {
    extern __shared__ char smem[];
    uint32_t sb = (uint32_t)__cvta_generic_to_shared(smem);

    int tid = threadIdx.x;
    int lane = tid & 31, wid = tid >> 5;
    int wr = wid >> 1, wc = wid & 1;
    int g = lane >> 2, t = lane & 3;
    int grp = lane >> 3, l7 = lane & 7;
    int bm = blockIdx.y * 128, bn = blockIdx.x * 128;

    const __half* Ablk = A + (size_t)bm * K;
    const __half* Wblk = W + (size_t)bn * K;

    float c[4][8][4];
    #pragma unroll
    for (int i = 0; i < 4; i++)
        #pragma unroll
        for (int j = 0; j < 8; j++)
            #pragma unroll
            for (int r = 0; r < 4; r++) c[i][j][r] = 0.f;

    int lrow0 = tid >> 3;
    int lseg  = tid & 7;
    uint32_t lcol = (uint32_t)((lseg ^ (lrow0 & 7)) << 4);
    auto load_stage = [&](int slot, int k0) {
        char* sbase = smem + slot * STG_B;
        #pragma unroll
        for (int i = 0; i < 16; i++) {
            int row = lrow0 + (i & 7) * 16;
            int isB = i >> 3;
            const __half* src = (isB ? Wblk : Ablk) + (size_t)row * K + k0 + lseg * 8;
            char* dst = sbase + isB * 16384 + row * 128 + lcol;
            cp_async16(dst, src);
        }
        cp_commit();
    };

    int NK = K / 64;
    load_stage(0, 0);
    load_stage(1, 64);

    int rowoffA = (grp & 1) * 8, segoffA = grp >> 1;
    int rowoffB = (grp >> 1) * 8, segoffB = grp & 1;

    uint32_t afr[2][4][4], bfr[2][8][2];

    auto load_frags = [&](int j, int buf, uint32_t sA, uint32_t sB) {
        #pragma unroll
        for (int ti = 0; ti < 4; ti++) {
            int row = wr * 64 + ti * 16 + rowoffA + l7;
            uint32_t addr = sA + (row << 7) + (((2 * j + segoffA) ^ (row & 7)) << 4);
            ldsm4(afr[buf][ti][0], afr[buf][ti][1], afr[buf][ti][2], afr[buf][ti][3], addr);
        }
        #pragma unroll
        for (int tp = 0; tp < 4; tp++) {
            int row = wc * 64 + tp * 16 + rowoffB + l7;
            uint32_t addr = sB + (row << 7) + (((2 * j + segoffB) ^ (row & 7)) << 4);
            uint32_t r0, r1, r2, r3;
            ldsm4(r0, r1, r2, r3, addr);
            bfr[buf][2 * tp][0] = r0;     bfr[buf][2 * tp][1] = r1;
            bfr[buf][2 * tp + 1][0] = r2; bfr[buf][2 * tp + 1][1] = r3;
        }
    };

    for (int kc = 0; kc < NK; kc++) {
        int slot = kc % NSTG;
        cp_wait<1>();
        __syncthreads();

        if (kc + 2 < NK) load_stage((kc + 2) % NSTG, (kc + 2) * 64);
        else cp_commit();

        uint32_t sA = sb + slot * STG_B;
        uint32_t sB = sA + 16384;

        load_frags(0, 0, sA, sB);
        #pragma unroll
        for (int j = 0; j < 4; j++) {
            int cur = j & 1;
            if (j < 3) load_frags(j + 1, cur ^ 1, sA, sB);
            #pragma unroll
            for (int ti = 0; ti < 4; ti++)
                #pragma unroll
                for (int tj = 0; tj < 8; tj++) {
                    asm volatile(
                        "mma.sync.aligned.m16n8k16.row.col.f32.f16.f16.f32 "
                        "{%0,%1,%2,%3}, {%4,%5,%6,%7}, {%8,%9}, {%0,%1,%2,%3};\n"
                        : "+f"(c[ti][tj][0]), "+f"(c[ti][tj][1]),
                          "+f"(c[ti][tj][2]), "+f"(c[ti][tj][3])
                        : "r"(afr[cur][ti][0]), "r"(afr[cur][ti][1]),
                          "r"(afr[cur][ti][2]), "r"(afr[cur][ti][3]),
                          "r"(bfr[cur][tj][0]), "r"(bfr[cur][tj][1]));
                }
        }
    }

    // epilogue
    #pragma unroll
    for (int ti = 0; ti < 4; ti++) {
        int r0 = bm + wr * 64 + ti * 16 + g;
        #pragma unroll
        for (int tj = 0; tj < 8; tj++) {
            int cn = bn + wc * 64 + tj * 8 + t * 2;
            float v[4] = {c[ti][tj][0], c[ti][tj][1], c[ti][tj][2], c[ti][tj][3]};
            if (BIAS) {
                float b0 = bias[cn], b1 = bias[cn + 1];
                v[0] += b0; v[1] += b1; v[2] += b0; v[3] += b1;
            }
            if (GELU) {
                #pragma unroll
                for (int q = 0; q < 4; q++)
                    v[q] = 0.5f * v[q] * (1.0f + erff(v[q] * 0.70710678118654752f));
            }
            if (RES) {
                float2 r0v = *(const float2*)&res[(size_t)r0 * Nout + cn];
                float2 r1v = *(const float2*)&res[(size_t)(r0 + 8) * Nout + cn];
                v[0] += r0v.x; v[1] += r0v.y; v[2] += r1v.x; v[3] += r1v.y;
            }
            if (OUTH) {
                *(__half2*)&outh[(size_t)r0 * Nout + cn]       = __floats2half2_rn(v[0], v[1]);
                *(__half2*)&outh[(size_t)(r0 + 8) * Nout + cn] = __floats2half2_rn(v[2], v[3]);
            } else {
                *(float2*)&outf[(size_t)r0 * Nout + cn]       = make_float2(v[0], v[1]);
                *(float2*)&outf[(size_t)(r0 + 8) * Nout + cn] = make_float2(v[2], v[3]);
            }
        }
    }
}

// ---------------- fused attention v4: tensor-core scoring + R12 selection ----------------
// Q,K staged swizzled (SW128) in smem; each warp computes a 16x208 score strip via
// m16n8k16 (fp32 accumulate, scale folded in), dumps fp16 scores to a per-warp smem
// buffer, then does top-16 with ordered-u16 keys + SHFL butterfly (R12-proven).
#define APADN   208                      // 196 padded to 13 strips of 16
#define ASTRIPS 13
#define SSTRIDE 424                      // bytes per score row (212 halves): conflict-free
#define QK_TILE (APADN * 128)            // 26624 B each
#define SS_WARP (16 * SSTRIDE)           // 6784 B per warp
#define ATTN_SMEM (2 * QK_TILE + 8 * SS_WARP + 128)   // 107,648 B -> 2 blocks/SM

template <int TP0, int NTP>
__device__ __forceinline__ void attn_score_pass(uint32_t Qb, uint32_t Kb, uint32_t Sw,
                                                int Rb, int grp, int l7, int g, int t) {
    int rowoffA = (grp & 1) * 8, segoffA = grp >> 1;
    int rowoffB = (grp >> 1) * 8, segoffB = grp & 1;
    float acc[2 * NTP][4];
    #pragma unroll
    for (int f = 0; f < 2 * NTP; f++) {
        acc[f][0] = 0.f; acc[f][1] = 0.f; acc[f][2] = 0.f; acc[f][3] = 0.f;
    }
    #pragma unroll
    for (int j = 0; j < 4; j++) {
        uint32_t a0, a1, a2, a3;
        {
            int row = Rb + rowoffA + l7;
            uint32_t addr = Qb + (row << 7) + (((2 * j + segoffA) ^ (row & 7)) << 4);
            ldsm4(a0, a1, a2, a3, addr);
        }
        uint32_t bf[2 * NTP][2];
        #pragma unroll
        for (int i = 0; i < NTP; i++) {
            int row = (TP0 + i) * 16 + rowoffB + l7;
            uint32_t addr = Kb + (row << 7) + (((2 * j + segoffB) ^ (row & 7)) << 4);
            uint32_t r0, r1, r2, r3;
            ldsm4(r0, r1, r2, r3, addr);
            bf[2 * i][0] = r0;     bf[2 * i][1] = r1;
            bf[2 * i + 1][0] = r2; bf[2 * i + 1][1] = r3;
        }
        #pragma unroll
        for (int f = 0; f < 2 * NTP; f++) {
            asm volatile(
                "mma.sync.aligned.m16n8k16.row.col.f32.f16.f16.f32 "
                "{%0,%1,%2,%3}, {%4,%5,%6,%7}, {%8,%9}, {%0,%1,%2,%3};\n"
                : "+f"(acc[f][0]), "+f"(acc[f][1]), "+f"(acc[f][2]), "+f"(acc[f][3])
                : "r"(a0), "r"(a1), "r"(a2), "r"(a3), "r"(bf[f][0]), "r"(bf[f][1]));
        }
    }
    // scale + pack fp16 + store to per-warp score buffer
    #pragma unroll
    for (int f = 0; f < 2 * NTP; f++) {
        int col0 = 8 * (2 * TP0 + f) + 2 * t;
        __half2 lo = __floats2half2_rn(acc[f][0] * SCALE_, acc[f][1] * SCALE_);
        __half2 hi = __floats2half2_rn(acc[f][2] * SCALE_, acc[f][3] * SCALE_);
        sts32(Sw + g * SSTRIDE + col0 * 2, *(uint32_t*)&lo);
        sts32(Sw + (g + 8) * SSTRIDE + col0 * 2, *(uint32_t*)&hi);
    }
}

__global__ __launch_bounds__(256, 2) void attn_topk_kernel(const __half* __restrict__ qk,
                                                           __half* __restrict__ a) {
    int bh = blockIdx.x;
    int b = bh / H_, h = bh % H_;
    extern __shared__ char asmem[];
    uint32_t base = (uint32_t)__cvta_generic_to_shared(asmem);
    uint32_t Qb = base, Kb = base + QK_TILE;
    int tid = threadIdx.x, lane = tid & 31, warp = tid >> 5;
    int grp = lane >> 3, l7 = lane & 7, g = lane >> 2, t = lane & 3;
    uint32_t Sw = base + 2 * QK_TILE + warp * SS_WARP;

    // stage Q,K (swizzled, 16B chunks); zero-fill padded rows
    const __half* src = qk + (size_t)b * N_ * (2 * C_);
    for (int e = tid; e < APADN * 8 * 2; e += 256) {
        int isK = e & 1;
        int m = e >> 1;
        int row = m >> 3, seg = m & 7;
        uint32_t dst = (isK ? Kb : Qb) + row * 128 + (((seg ^ (row & 7))) << 4);
        if (row < N_) {
            cp_async16a(dst, src + (size_t)row * (2 * C_) + (isK ? C_ : 0) + h * HD_ + seg * 8);
        } else {
            asm volatile("st.shared.v4.b32 [%0], {%1,%1,%1,%1};\n" :: "r"(dst), "r"(0u) : "memory");
        }
    }
    cp_commit();
    cp_wait<0>();
    __syncthreads();

    for (int sidx = warp; sidx < ASTRIPS; sidx += 8) {
        int Rb = sidx * 16;
        attn_score_pass<0, 7>(Qb, Kb, Sw, Rb, grp, l7, g, t);
        attn_score_pass<7, 6>(Qb, Kb, Sw, Rb, grp, l7, g, t);
        __syncwarp();

        for (int sub = 0; sub < 16; sub++) {
            int r = Rb + sub;
            if (r >= N_) break;
            uint32_t key[7];
            #pragma unroll
            for (int t2 = 0; t2 < 7; t2++) {
                int jq = lane + 32 * t2;
                unsigned short bits;
                asm volatile("ld.shared.u16 %0, [%1];\n"
                             : "=h"(bits) : "r"(Sw + sub * SSTRIDE + jq * 2));
                uint32_t o = (bits & 0x8000u) ? (uint32_t)((~bits) & 0xFFFFu)
                                              : (uint32_t)(bits | 0x8000u);
                key[t2] = (jq < N_) ? ((o << 16) | (uint32_t)(lane << 3) | (uint32_t)t2) : 0u;
            }
            float top[16];
            #pragma unroll
            for (int sel = 0; sel < TOPK_; sel++) {
                uint32_t m = key[0];
                #pragma unroll
                for (int t2 = 1; t2 < 7; t2++) m = (key[t2] > m) ? key[t2] : m;
                #pragma unroll
                for (int o = 16; o > 0; o >>= 1) {
                    uint32_t om = __shfl_xor_sync(0xffffffffu, m, o);
                    m = (om > m) ? om : m;
                }
                uint32_t k16 = m >> 16;
                uint32_t bits = (k16 & 0x8000u) ? (k16 ^ 0x8000u) : ((~k16) & 0xFFFFu);
                top[sel] = __half2float(__ushort_as_half((unsigned short)bits));
                if (lane == (int)((m >> 3) & 31u)) {
                    int sl = (int)(m & 7u);
                    #pragma unroll
                    for (int t2 = 0; t2 < 7; t2++) if (t2 == sl) key[t2] = 0u;
                }
            }
            float ssum = 0.f;
            #pragma unroll
            for (int t2 = 0; t2 < TOPK_; t2++) ssum += expf(top[t2] - top[0]);
            if (lane < TOPK_) {
                float val = expf(top[lane] - top[0]) / ssum;
                a[((size_t)(b * N_ + r)) * (H_ * TOPK_) + h * TOPK_ + lane] = __float2half(val);
            }
        }
        __syncwarp();
    }
}

// ---------------- launch ----------------
extern "C" void kernel_launch(void* const* d_in, const int* in_sizes, int n_in,
                              void* d_out, int out_size) {
    const float* x      = (const float*)d_in[0];
    const float* n1g    = (const float*)d_in[1];
    const float* n1b    = (const float*)d_in[2];
    const float* qk_w   = (const float*)d_in[3];
    const float* proj_w = (const float*)d_in[4];
    const float* proj_b = (const float*)d_in[5];
    const float* n2g    = (const float*)d_in[6];
    const float* n2b    = (const float*)d_in[7];
    const float* fc1_w  = (const float*)d_in[8];
    const float* fc1_b  = (const float*)d_in[9];
    const float* fc2_w  = (const float*)d_in[10];
    const float* fc2_b  = (const float*)d_in[11];
    float* out = (float*)d_out;

    __half *h_h, *qk_h, *a_h, *hid_h, *qkw_h, *pw_h, *f1w_h, *f2w_h;
    float *x1;
    cudaGetSymbolAddress((void**)&h_h,   g_h_h);
    cudaGetSymbolAddress((void**)&qk_h,  g_qk_h);
    cudaGetSymbolAddress((void**)&a_h,   g_a_h);
    cudaGetSymbolAddress((void**)&x1,    g_x1);
    cudaGetSymbolAddress((void**)&hid_h, g_hid_h);
    cudaGetSymbolAddress((void**)&qkw_h, g_qkw_h);
    cudaGetSymbolAddress((void**)&pw_h,  g_pw_h);
    cudaGetSymbolAddress((void**)&f1w_h, g_f1w_h);
    cudaGetSymbolAddress((void**)&f2w_h, g_f2w_h);

    cudaFuncSetAttribute((const void*)gemm_h<false,false,false,true>, cudaFuncAttributeMaxDynamicSharedMemorySize, SMEM_SZ);
    cudaFuncSetAttribute((const void*)gemm_h<true,false,true,false>,  cudaFuncAttributeMaxDynamicSharedMemorySize, SMEM_SZ);
    cudaFuncSetAttribute((const void*)gemm_h<true,true,false,true>,   cudaFuncAttributeMaxDynamicSharedMemorySize, SMEM_SZ);

    // merged weight conversions (fp32 -> fp16)
    {
        int n0 = 2 * C_ * C_;
        int n1 = C_ * H_ * TOPK_;
        int n2 = HID_ * C_;
        int n3 = C_ * HID_;
        int total = n0 + n1 + n2 + n3;
        cvt4_kernel<<<(total / 4 + 255) / 256, 256>>>(qk_w, qkw_h, n0,
                                                      proj_w, pw_h, n1,
                                                      fc1_w, f1w_h, n2,
                                                      fc2_w, f2w_h, n3);
    }

    // 1. LN1 -> fp16
    ln_kernel<<<M_, 192>>>(x, n1g, n1b, h_h);

    // 2. qk = h @ qk_w^T   [M, 1536], K=768 (fp16 out)
    gemm_h<false, false, false, true><<<dim3((2 * C_) / 128, M_ / 128), 128, SMEM_SZ>>>(
        h_h, qkw_h, nullptr, nullptr, nullptr, qk_h, 2 * C_, C_);

    // 3. attention -> a fp16 [M, 192]
    cudaFuncSetAttribute(attn_topk_kernel, cudaFuncAttributeMaxDynamicSharedMemorySize, ATTN_SMEM);
    attn_topk_kernel<<<B_ * H_, 256, ATTN_SMEM>>>(qk_h, a_h);

    // 4. x1 = x + a @ proj_w^T + proj_b   [M, 768], K=192
    gemm_h<true, false, true, false><<<dim3(C_ / 128, M_ / 128), 128, SMEM_SZ>>>(
        a_h, pw_h, proj_b, x, x1, nullptr, C_, H_ * TOPK_);

    // 5. LN2 -> fp16
    ln_kernel<<<M_, 192>>>(x1, n2g, n2b, h_h);

    // 6. hid = gelu(h @ fc1_w^T + fc1_b) -> fp16 [M, 3072], K=768
    gemm_h<true, true, false, true><<<dim3(HID_ / 128, M_ / 128), 128, SMEM_SZ>>>(
        h_h, f1w_h, fc1_b, nullptr, nullptr, hid_h, HID_, C_);

    // 7. out = x1 + hid @ fc2_w^T + fc2_b  [M, 768], K=3072
    gemm_h<true, false, true, false><<<dim3(C_ / 128, M_ / 128), 128, SMEM_SZ>>>(
        hid_h, f2w_h, fc2_b, x1, out, nullptr, C_, HID_);
}

// round 17
// speedup vs baseline: 1.4231x; 1.0570x over previous
#include <cuda_runtime.h>
#include <cuda_fp16.h>
#include <math.h>
#include <stdint.h>

#define B_   64
#define N_   196
#define C_   768
#define H_   12
#define HD_  64
#define TOPK_ 16
#define HID_ 3072
#define M_   (B_ * N_)          // 12544
#define SCALE_ 0.125f
#define EPS_ 1e-5f

// ---------------- scratch (device globals) ----------------
__device__ __half g_h_h  [(size_t)M_ * C_];
__device__ __half g_qk_h [(size_t)M_ * 2 * C_];
__device__ __half g_a_h  [(size_t)M_ * H_ * TOPK_];
__device__ float  g_x1   [(size_t)M_ * C_];
__device__ __half g_hid_h[(size_t)M_ * HID_];
// fp16 weights
__device__ __half g_qkw_h[(size_t)2 * C_ * C_];
__device__ __half g_pw_h [(size_t)C_ * H_ * TOPK_];
__device__ __half g_f1w_h[(size_t)HID_ * C_];
__device__ __half g_f2w_h[(size_t)C_ * HID_];

// ---------------- helpers ----------------
__device__ __forceinline__ void cp_async16(void* smem, const void* gmem) {
    uint32_t s = (uint32_t)__cvta_generic_to_shared(smem);
    asm volatile("cp.async.cg.shared.global [%0], [%1], 16;\n" :: "r"(s), "l"(gmem));
}
__device__ __forceinline__ void cp_async16a(uint32_t s, const void* gmem) {
    asm volatile("cp.async.cg.shared.global [%0], [%1], 16;\n" :: "r"(s), "l"(gmem));
}
__device__ __forceinline__ void cp_commit() { asm volatile("cp.async.commit_group;\n"); }
template <int Np>
__device__ __forceinline__ void cp_wait() { asm volatile("cp.async.wait_group %0;\n" :: "n"(Np) : "memory"); }
__device__ __forceinline__ void ldsm4(uint32_t& r0, uint32_t& r1, uint32_t& r2, uint32_t& r3,
                                      uint32_t addr) {
    asm volatile("ldmatrix.sync.aligned.m8n8.x4.shared.b16 {%0,%1,%2,%3}, [%4];\n"
                 : "=r"(r0), "=r"(r1), "=r"(r2), "=r"(r3) : "r"(addr));
}
__device__ __forceinline__ void sts32(uint32_t addr, uint32_t val) {
    asm volatile("st.shared.b32 [%0], %1;\n" :: "r"(addr), "r"(val) : "memory");
}
__device__ __forceinline__ void stsf(uint32_t addr, float val) {
    asm volatile("st.shared.f32 [%0], %1;\n" :: "r"(addr), "f"(val) : "memory");
}
__device__ __forceinline__ float ldsf(uint32_t addr) {
    float v;
    asm volatile("ld.shared.f32 %0, [%1];\n" : "=f"(v) : "r"(addr));
    return v;
}

// ---------------- merged weight fp32 -> fp16 (float4 vectorized) ----------------
__global__ void cvt4_kernel(const float* __restrict__ s0, __half* __restrict__ d0, int n0,
                            const float* __restrict__ s1, __half* __restrict__ d1, int n1,
                            const float* __restrict__ s2, __half* __restrict__ d2, int n2,
                            const float* __restrict__ s3, __half* __restrict__ d3, int n3) {
    int i = (blockIdx.x * 256 + threadIdx.x) * 4;
    const float* s; __half* d; int off;
    if (i < n0)                { s = s0; d = d0; off = 0; }
    else if (i < n0 + n1)      { s = s1; d = d1; off = n0; }
    else if (i < n0 + n1 + n2) { s = s2; d = d2; off = n0 + n1; }
    else if (i < n0 + n1 + n2 + n3) { s = s3; d = d3; off = n0 + n1 + n2; }
    else return;
    int j = i - off;
    float4 v = *(const float4*)&s[j];
    __half2 h0 = __floats2half2_rn(v.x, v.y);
    __half2 h1 = __floats2half2_rn(v.z, v.w);
    *(uint2*)&d[j] = make_uint2(*(uint32_t*)&h0, *(uint32_t*)&h1);
}

// ---------------- LayerNorm -> fp16 (float4 vectorized, 192 threads) ----------------
__global__ void ln_kernel(const float* __restrict__ x, const float* __restrict__ g,
                          const float* __restrict__ b, __half* __restrict__ out) {
    int row = blockIdx.x;
    const float4* xr = (const float4*)(x + (size_t)row * C_);
    int tid = threadIdx.x, lane = tid & 31, warp = tid >> 5;   // 192 threads, 6 warps

    float4 v = xr[tid];
    float s  = v.x + v.y + v.z + v.w;
    float s2 = v.x * v.x + v.y * v.y + v.z * v.z + v.w * v.w;
    #pragma unroll
    for (int o = 16; o > 0; o >>= 1) {
        s  += __shfl_xor_sync(0xffffffffu, s,  o);
        s2 += __shfl_xor_sync(0xffffffffu, s2, o);
    }
    __shared__ float shs[6], shs2[6], sh_mu, sh_inv;
    if (lane == 0) { shs[warp] = s; shs2[warp] = s2; }
    __syncthreads();
    if (tid == 0) {
        float ts = 0.f, ts2 = 0.f;
        #pragma unroll
        for (int w = 0; w < 6; w++) { ts += shs[w]; ts2 += shs2[w]; }
        float mu = ts / C_;
        sh_mu = mu; sh_inv = rsqrtf(ts2 / C_ - mu * mu + EPS_);
    }
    __syncthreads();
    float mu = sh_mu, inv = sh_inv;
    float4 gv = ((const float4*)g)[tid];
    float4 bv = ((const float4*)b)[tid];
    float o0 = (v.x - mu) * inv * gv.x + bv.x;
    float o1 = (v.y - mu) * inv * gv.y + bv.y;
    float o2 = (v.z - mu) * inv * gv.z + bv.z;
    float o3 = (v.w - mu) * inv * gv.w + bv.w;
    __half2 h0 = __floats2half2_rn(o0, o1);
    __half2 h1 = __floats2half2_rn(o2, o3);
    *(uint2*)&out[(size_t)row * C_ + tid * 4] = make_uint2(*(uint32_t*)&h0, *(uint32_t*)&h1);
}

// ---------------- FP16 mma.sync GEMM (frag double-buffered) ----------------
#define STG_B 32768               // (128+128) rows * 128 B
#define NSTG  3
#define SMEM_SZ (NSTG * STG_B)

template <bool BIAS, bool GELU, bool RES, bool OUTH>
__global__ __launch_bounds__(128, 2) void gemm_h(
        const __half* __restrict__ A, const __half* __restrict__ W,
        const float* __restrict__ bias, const float* __restrict__ res,
        float* __restrict__ outf, __half* __restrict__ outh, int Nout, int K) {
    extern __shared__ char smem[];
    uint32_t sb = (uint32_t)__cvta_generic_to_shared(smem);

    int tid = threadIdx.x;
    int lane = tid & 31, wid = tid >> 5;
    int wr = wid >> 1, wc = wid & 1;
    int g = lane >> 2, t = lane & 3;
    int grp = lane >> 3, l7 = lane & 7;
    int bm = blockIdx.y * 128, bn = blockIdx.x * 128;

    const __half* Ablk = A + (size_t)bm * K;
    const __half* Wblk = W + (size_t)bn * K;

    float c[4][8][4];
    #pragma unroll
    for (int i = 0; i < 4; i++)
        #pragma unroll
        for (int j = 0; j < 8; j++)
            #pragma unroll
            for (int r = 0; r < 4; r++) c[i][j][r] = 0.f;

    int lrow0 = tid >> 3;
    int lseg  = tid & 7;
    uint32_t lcol = (uint32_t)((lseg ^ (lrow0 & 7)) << 4);
    auto load_stage = [&](int slot, int k0) {
        char* sbase = smem + slot * STG_B;
        #pragma unroll
        for (int i = 0; i < 16; i++) {
            int row = lrow0 + (i & 7) * 16;
            int isB = i >> 3;
            const __half* src = (isB ? Wblk : Ablk) + (size_t)row * K + k0 + lseg * 8;
            char* dst = sbase + isB * 16384 + row * 128 + lcol;
            cp_async16(dst, src);
        }
        cp_commit();
    };

    int NK = K / 64;
    load_stage(0, 0);
    load_stage(1, 64);

    int rowoffA = (grp & 1) * 8, segoffA = grp >> 1;
    int rowoffB = (grp >> 1) * 8, segoffB = grp & 1;

    uint32_t afr[2][4][4], bfr[2][8][2];

    auto load_frags = [&](int j, int buf, uint32_t sA, uint32_t sB) {
        #pragma unroll
        for (int ti = 0; ti < 4; ti++) {
            int row = wr * 64 + ti * 16 + rowoffA + l7;
            uint32_t addr = sA + (row << 7) + (((2 * j + segoffA) ^ (row & 7)) << 4);
            ldsm4(afr[buf][ti][0], afr[buf][ti][1], afr[buf][ti][2], afr[buf][ti][3], addr);
        }
        #pragma unroll
        for (int tp = 0; tp < 4; tp++) {
            int row = wc * 64 + tp * 16 + rowoffB + l7;
            uint32_t addr = sB + (row << 7) + (((2 * j + segoffB) ^ (row & 7)) << 4);
            uint32_t r0, r1, r2, r3;
            ldsm4(r0, r1, r2, r3, addr);
            bfr[buf][2 * tp][0] = r0;     bfr[buf][2 * tp][1] = r1;
            bfr[buf][2 * tp + 1][0] = r2; bfr[buf][2 * tp + 1][1] = r3;
        }
    };

    for (int kc = 0; kc < NK; kc++) {
        int slot = kc % NSTG;
        cp_wait<1>();
        __syncthreads();

        if (kc + 2 < NK) load_stage((kc + 2) % NSTG, (kc + 2) * 64);
        else cp_commit();

        uint32_t sA = sb + slot * STG_B;
        uint32_t sB = sA + 16384;

        load_frags(0, 0, sA, sB);
        #pragma unroll
        for (int j = 0; j < 4; j++) {
            int cur = j & 1;
            if (j < 3) load_frags(j + 1, cur ^ 1, sA, sB);
            #pragma unroll
            for (int ti = 0; ti < 4; ti++)
                #pragma unroll
                for (int tj = 0; tj < 8; tj++) {
                    asm volatile(
                        "mma.sync.aligned.m16n8k16.row.col.f32.f16.f16.f32 "
                        "{%0,%1,%2,%3}, {%4,%5,%6,%7}, {%8,%9}, {%0,%1,%2,%3};\n"
                        : "+f"(c[ti][tj][0]), "+f"(c[ti][tj][1]),
                          "+f"(c[ti][tj][2]), "+f"(c[ti][tj][3])
                        : "r"(afr[cur][ti][0]), "r"(afr[cur][ti][1]),
                          "r"(afr[cur][ti][2]), "r"(afr[cur][ti][3]),
                          "r"(bfr[cur][tj][0]), "r"(bfr[cur][tj][1]));
                }
        }
    }

    // epilogue
    #pragma unroll
    for (int ti = 0; ti < 4; ti++) {
        int r0 = bm + wr * 64 + ti * 16 + g;
        #pragma unroll
        for (int tj = 0; tj < 8; tj++) {
            int cn = bn + wc * 64 + tj * 8 + t * 2;
            float v[4] = {c[ti][tj][0], c[ti][tj][1], c[ti][tj][2], c[ti][tj][3]};
            if (BIAS) {
                float b0 = bias[cn], b1 = bias[cn + 1];
                v[0] += b0; v[1] += b1; v[2] += b0; v[3] += b1;
            }
            if (GELU) {
                #pragma unroll
                for (int q = 0; q < 4; q++)
                    v[q] = 0.5f * v[q] * (1.0f + erff(v[q] * 0.70710678118654752f));
            }
            if (RES) {
                float2 r0v = *(const float2*)&res[(size_t)r0 * Nout + cn];
                float2 r1v = *(const float2*)&res[(size_t)(r0 + 8) * Nout + cn];
                v[0] += r0v.x; v[1] += r0v.y; v[2] += r1v.x; v[3] += r1v.y;
            }
            if (OUTH) {
                *(__half2*)&outh[(size_t)r0 * Nout + cn]       = __floats2half2_rn(v[0], v[1]);
                *(__half2*)&outh[(size_t)(r0 + 8) * Nout + cn] = __floats2half2_rn(v[2], v[3]);
            } else {
                *(float2*)&outf[(size_t)r0 * Nout + cn]       = make_float2(v[0], v[1]);
                *(float2*)&outf[(size_t)(r0 + 8) * Nout + cn] = make_float2(v[2], v[3]);
            }
        }
    }
}

// ---------------- fused attention v5: tensor-core scoring + 2-row-ILP selection ----------------
// Scoring as in v4 (m16n8k16, fp32 acc, scale folded). Selection: 2 rows interleaved
// per iteration (dual independent shuffle chains), incremental lane-max, selected
// values staged in a 128B smem scratch (frees the top[16] register array).
#define APADN   208
#define ASTRIPS 13
#define SSTRIDE 424                      // bytes per score row (212 halves)
#define QK_TILE (APADN * 128)            // 26624 B each
#define SS_WARP (16 * SSTRIDE + 128)     // + 128B top-value scratch (2 rows x 16 f32)
#define ATTN_SMEM (2 * QK_TILE + 8 * SS_WARP + 128)   // 108,672 B -> 2 blocks/SM

__device__ __forceinline__ float key_to_float(uint32_t m) {
    uint32_t k16 = m >> 16;
    uint32_t bits = (k16 & 0x8000u) ? (k16 ^ 0x8000u) : ((~k16) & 0xFFFFu);
    return __half2float(__ushort_as_half((unsigned short)bits));
}

template <int TP0, int NTP>
__device__ __forceinline__ void attn_score_pass(uint32_t Qb, uint32_t Kb, uint32_t Sw,
                                                int Rb, int grp, int l7, int g, int t) {
    int rowoffA = (grp & 1) * 8, segoffA = grp >> 1;
    int rowoffB = (grp >> 1) * 8, segoffB = grp & 1;
    float acc[2 * NTP][4];
    #pragma unroll
    for (int f = 0; f < 2 * NTP; f++) {
        acc[f][0] = 0.f; acc[f][1] = 0.f; acc[f][2] = 0.f; acc[f][3] = 0.f;
    }
    #pragma unroll
    for (int j = 0; j < 4; j++) {
        uint32_t a0, a1, a2, a3;
        {
            int row = Rb + rowoffA + l7;
            uint32_t addr = Qb + (row << 7) + (((2 * j + segoffA) ^ (row & 7)) << 4);
            ldsm4(a0, a1, a2, a3, addr);
        }
        uint32_t bf[2 * NTP][2];
        #pragma unroll
        for (int i = 0; i < NTP; i++) {
            int row = (TP0 + i) * 16 + rowoffB + l7;
            uint32_t addr = Kb + (row << 7) + (((2 * j + segoffB) ^ (row & 7)) << 4);
            uint32_t r0, r1, r2, r3;
            ldsm4(r0, r1, r2, r3, addr);
            bf[2 * i][0] = r0;     bf[2 * i][1] = r1;
            bf[2 * i + 1][0] = r2; bf[2 * i + 1][1] = r3;
        }
        #pragma unroll
        for (int f = 0; f < 2 * NTP; f++) {
            asm volatile(
                "mma.sync.aligned.m16n8k16.row.col.f32.f16.f16.f32 "
                "{%0,%1,%2,%3}, {%4,%5,%6,%7}, {%8,%9}, {%0,%1,%2,%3};\n"
                : "+f"(acc[f][0]), "+f"(acc[f][1]), "+f"(acc[f][2]), "+f"(acc[f][3])
                : "r"(a0), "r"(a1), "r"(a2), "r"(a3), "r"(bf[f][0]), "r"(bf[f][1]));
        }
    }
    #pragma unroll
    for (int f = 0; f < 2 * NTP; f++) {
        int col0 = 8 * (2 * TP0 + f) + 2 * t;
        __half2 lo = __floats2half2_rn(acc[f][0] * SCALE_, acc[f][1] * SCALE_);
        __half2 hi = __floats2half2_rn(acc[f][2] * SCALE_, acc[f][3] * SCALE_);
        sts32(Sw + g * SSTRIDE + col0 * 2, *(uint32_t*)&lo);
        sts32(Sw + (g + 8) * SSTRIDE + col0 * 2, *(uint32_t*)&hi);
    }
}

__global__ __launch_bounds__(256, 2) void attn_topk_kernel(const __half* __restrict__ qk,
                                                           __half* __restrict__ a) {
    int bh = blockIdx.x;
    int b = bh / H_, h = bh % H_;
    extern __shared__ char asmem[];
    uint32_t base = (uint32_t)__cvta_generic_to_shared(asmem);
    uint32_t Qb = base, Kb = base + QK_TILE;
    int tid = threadIdx.x, lane = tid & 31, warp = tid >> 5;
    int grp = lane >> 3, l7 = lane & 7, g = lane >> 2, t = lane & 3;
    uint32_t Sw = base + 2 * QK_TILE + warp * SS_WARP;
    uint32_t Tv = Sw + 16 * SSTRIDE;       // 128B scratch: rowA 16 f32, rowB 16 f32

    // stage Q,K (swizzled); zero-fill padded rows
    const __half* src = qk + (size_t)b * N_ * (2 * C_);
    for (int e = tid; e < APADN * 8 * 2; e += 256) {
        int isK = e & 1;
        int m = e >> 1;
        int row = m >> 3, seg = m & 7;
        uint32_t dst = (isK ? Kb : Qb) + row * 128 + (((seg ^ (row & 7))) << 4);
        if (row < N_) {
            cp_async16a(dst, src + (size_t)row * (2 * C_) + (isK ? C_ : 0) + h * HD_ + seg * 8);
        } else {
            asm volatile("st.shared.v4.b32 [%0], {%1,%1,%1,%1};\n" :: "r"(dst), "r"(0u) : "memory");
        }
    }
    cp_commit();
    cp_wait<0>();
    __syncthreads();

    for (int sidx = warp; sidx < ASTRIPS; sidx += 8) {
        int Rb = sidx * 16;
        attn_score_pass<0, 7>(Qb, Kb, Sw, Rb, grp, l7, g, t);
        attn_score_pass<7, 6>(Qb, Kb, Sw, Rb, grp, l7, g, t);
        __syncwarp();

        for (int sub = 0; sub < 16; sub += 2) {
            int r0 = Rb + sub;
            if (r0 >= N_) break;
            int r1 = r0 + 1;
            bool has1 = (r1 < N_);

            // build ordered-u32 keys for both rows
            uint32_t kA[7], kB[7];
            #pragma unroll
            for (int t2 = 0; t2 < 7; t2++) {
                int jq = lane + 32 * t2;
                unsigned short bA, bB;
                asm volatile("ld.shared.u16 %0, [%1];\n" : "=h"(bA) : "r"(Sw + sub * SSTRIDE + jq * 2));
                asm volatile("ld.shared.u16 %0, [%1];\n" : "=h"(bB) : "r"(Sw + (sub + 1) * SSTRIDE + jq * 2));
                uint32_t oA = (bA & 0x8000u) ? (uint32_t)((~bA) & 0xFFFFu) : (uint32_t)(bA | 0x8000u);
                uint32_t oB = (bB & 0x8000u) ? (uint32_t)((~bB) & 0xFFFFu) : (uint32_t)(bB | 0x8000u);
                uint32_t id = (uint32_t)(lane << 3) | (uint32_t)t2;
                bool ok = (jq < N_);
                kA[t2] = ok ? ((oA << 16) | id) : 0u;
                kB[t2] = ok ? ((oB << 16) | id) : 0u;
            }
            uint32_t lmA = kA[0], lmB = kB[0];
            #pragma unroll
            for (int t2 = 1; t2 < 7; t2++) {
                lmA = (kA[t2] > lmA) ? kA[t2] : lmA;
                lmB = (kB[t2] > lmB) ? kB[t2] : lmB;
            }

            #pragma unroll
            for (int sel = 0; sel < TOPK_; sel++) {
                uint32_t mA = lmA, mB = lmB;
                #pragma unroll
                for (int o = 16; o > 0; o >>= 1) {
                    uint32_t oA2 = __shfl_xor_sync(0xffffffffu, mA, o);
                    uint32_t oB2 = __shfl_xor_sync(0xffffffffu, mB, o);
                    mA = (oA2 > mA) ? oA2 : mA;
                    mB = (oB2 > mB) ? oB2 : mB;
                }
                if (lane == 0) {
                    stsf(Tv + sel * 4, key_to_float(mA));
                    stsf(Tv + 64 + sel * 4, key_to_float(mB));
                }
                if (lane == (int)((mA >> 3) & 31u)) {
                    int sl = (int)(mA & 7u);
                    #pragma unroll
                    for (int t2 = 0; t2 < 7; t2++) if (t2 == sl) kA[t2] = 0u;
                    lmA = kA[0];
                    #pragma unroll
                    for (int t2 = 1; t2 < 7; t2++) lmA = (kA[t2] > lmA) ? kA[t2] : lmA;
                }
                if (lane == (int)((mB >> 3) & 31u)) {
                    int sl = (int)(mB & 7u);
                    #pragma unroll
                    for (int t2 = 0; t2 < 7; t2++) if (t2 == sl) kB[t2] = 0u;
                    lmB = kB[0];
                    #pragma unroll
                    for (int t2 = 1; t2 < 7; t2++) lmB = (kB[t2] > lmB) ? kB[t2] : lmB;
                }
            }
            __syncwarp();

            // softmax for both rows from smem scratch
            float m0A = ldsf(Tv), m0B = ldsf(Tv + 64);
            float eA = 0.f, eB = 0.f;
            if (lane < TOPK_) {
                eA = expf(ldsf(Tv + lane * 4) - m0A);
                eB = expf(ldsf(Tv + 64 + lane * 4) - m0B);
            }
            float sA = eA, sB = eB;
            #pragma unroll
            for (int o = 8; o > 0; o >>= 1) {
                sA += __shfl_xor_sync(0xffffffffu, sA, o);
                sB += __shfl_xor_sync(0xffffffffu, sB, o);
            }
            if (lane < TOPK_) {
                a[((size_t)(b * N_ + r0)) * (H_ * TOPK_) + h * TOPK_ + lane] = __float2half(eA / sA);
                if (has1)
                    a[((size_t)(b * N_ + r1)) * (H_ * TOPK_) + h * TOPK_ + lane] = __float2half(eB / sB);
            }
            __syncwarp();
        }
        __syncwarp();
    }
}

// ---------------- launch ----------------
extern "C" void kernel_launch(void* const* d_in, const int* in_sizes, int n_in,
                              void* d_out, int out_size) {
    const float* x      = (const float*)d_in[0];
    const float* n1g    = (const float*)d_in[1];
    const float* n1b    = (const float*)d_in[2];
    const float* qk_w   = (const float*)d_in[3];
    const float* proj_w = (const float*)d_in[4];
    const float* proj_b = (const float*)d_in[5];
    const float* n2g    = (const float*)d_in[6];
    const float* n2b    = (const float*)d_in[7];
    const float* fc1_w  = (const float*)d_in[8];
    const float* fc1_b  = (const float*)d_in[9];
    const float* fc2_w  = (const float*)d_in[10];
    const float* fc2_b  = (const float*)d_in[11];
    float* out = (float*)d_out;

    __half *h_h, *qk_h, *a_h, *hid_h, *qkw_h, *pw_h, *f1w_h, *f2w_h;
    float *x1;
    cudaGetSymbolAddress((void**)&h_h,   g_h_h);
    cudaGetSymbolAddress((void**)&qk_h,  g_qk_h);
    cudaGetSymbolAddress((void**)&a_h,   g_a_h);
    cudaGetSymbolAddress((void**)&x1,    g_x1);
    cudaGetSymbolAddress((void**)&hid_h, g_hid_h);
    cudaGetSymbolAddress((void**)&qkw_h, g_qkw_h);
    cudaGetSymbolAddress((void**)&pw_h,  g_pw_h);
    cudaGetSymbolAddress((void**)&f1w_h, g_f1w_h);
    cudaGetSymbolAddress((void**)&f2w_h, g_f2w_h);

    cudaFuncSetAttribute((const void*)gemm_h<false,false,false,true>, cudaFuncAttributeMaxDynamicSharedMemorySize, SMEM_SZ);
    cudaFuncSetAttribute((const void*)gemm_h<true,false,true,false>,  cudaFuncAttributeMaxDynamicSharedMemorySize, SMEM_SZ);
    cudaFuncSetAttribute((const void*)gemm_h<true,true,false,true>,   cudaFuncAttributeMaxDynamicSharedMemorySize, SMEM_SZ);

    // merged weight conversions (fp32 -> fp16)
    {
        int n0 = 2 * C_ * C_;
        int n1 = C_ * H_ * TOPK_;
        int n2 = HID_ * C_;
        int n3 = C_ * HID_;
        int total = n0 + n1 + n2 + n3;
        cvt4_kernel<<<(total / 4 + 255) / 256, 256>>>(qk_w, qkw_h, n0,
                                                      proj_w, pw_h, n1,
                                                      fc1_w, f1w_h, n2,
                                                      fc2_w, f2w_h, n3);
    }

    // 1. LN1 -> fp16
    ln_kernel<<<M_, 192>>>(x, n1g, n1b, h_h);

    // 2. qk = h @ qk_w^T   [M, 1536], K=768 (fp16 out)
    gemm_h<false, false, false, true><<<dim3((2 * C_) / 128, M_ / 128), 128, SMEM_SZ>>>(
        h_h, qkw_h, nullptr, nullptr, nullptr, qk_h, 2 * C_, C_);

    // 3. attention -> a fp16 [M, 192]
    cudaFuncSetAttribute(attn_topk_kernel, cudaFuncAttributeMaxDynamicSharedMemorySize, ATTN_SMEM);
    attn_topk_kernel<<<B_ * H_, 256, ATTN_SMEM>>>(qk_h, a_h);

    // 4. x1 = x + a @ proj_w^T + proj_b   [M, 768], K=192
    gemm_h<true, false, true, false><<<dim3(C_ / 128, M_ / 128), 128, SMEM_SZ>>>(
        a_h, pw_h, proj_b, x, x1, nullptr, C_, H_ * TOPK_);

    // 5. LN2 -> fp16
    ln_kernel<<<M_, 192>>>(x1, n2g, n2b, h_h);

    // 6. hid = gelu(h @ fc1_w^T + fc1_b) -> fp16 [M, 3072], K=768
    gemm_h<true, true, false, true><<<dim3(HID_ / 128, M_ / 128), 128, SMEM_SZ>>>(
        h_h, f1w_h, fc1_b, nullptr, nullptr, hid_h, HID_, C_);

    // 7. out = x1 + hid @ fc2_w^T + fc2_b  [M, 768], K=3072
    gemm_h<true, false, true, false><<<dim3(C_ / 128, M_ / 128), 128, SMEM_SZ>>>(
        hid_h, f2w_h, fc2_b, x1, out, nullptr, C_, HID_);
}